// round 1
// baseline (speedup 1.0000x reference)
#include <cuda_runtime.h>
#include <math.h>

#define BB   2
#define TT   512
#define DD   512
#define NTOK 1024          // B*T
#define NTH  128           // threads per token-block
#define CPT  4             // d-values per thread (NTH*CPT = DD)

__device__ float g_sumsq;

__global__ void k_zero() { g_sumsq = 0.f; }

__device__ __forceinline__ float warp_sum(float v) {
    v += __shfl_down_sync(0xffffffffu, v, 16);
    v += __shfl_down_sync(0xffffffffu, v, 8);
    v += __shfl_down_sync(0xffffffffu, v, 4);
    v += __shfl_down_sync(0xffffffffu, v, 2);
    v += __shfl_down_sync(0xffffffffu, v, 1);
    return v;
}

__device__ __forceinline__ float block_sum(float v, float* red) {
    int lane = threadIdx.x & 31, w = threadIdx.x >> 5;
    v = warp_sum(v);
    __syncthreads();                  // protect red reuse across calls
    if (lane == 0) red[w] = v;
    __syncthreads();
    if (w == 0) {
        float x = (lane < NTH / 32) ? red[lane] : 0.f;
        x += __shfl_down_sync(0xffffffffu, x, 2);
        x += __shfl_down_sync(0xffffffffu, x, 1);
        if (lane == 0) red[0] = x;
    }
    __syncthreads();
    return red[0];
}

__global__ __launch_bounds__(NTH) void k_main(
    const int*   __restrict__ token_ids,
    const float* __restrict__ resonances,
    const float* __restrict__ emb_scales,
    const float* __restrict__ emb_shifts,
    const float* __restrict__ emb_norm,
    const float* __restrict__ W_enc,     // [512,24]
    const float* __restrict__ b_enc,     // [24]
    const float* __restrict__ W_dec,     // [24,512]
    const float* __restrict__ b_dec,     // [512]
    const float* __restrict__ ecc_strength,
    const float* __restrict__ energy_pres,
    float*       __restrict__ out)
{
    __shared__ float red[NTH / 32];
    __shared__ float smat[NTH * 25];     // proj partials, stride 25 (conflict-free)
    __shared__ float psum[24 * 5];
    __shared__ float sproj[24];
    __shared__ float slatt[12];
    __shared__ float scorr[24];
    __shared__ float s_ein2;

    const int tok = blockIdx.x;          // b*T + t
    const int t   = tok & (TT - 1);
    const int tid = threadIdx.x;
    const int d0  = tid * CPT;

    const float ecc   = ecc_strength[0];
    const float ep    = energy_pres[0];
    const float enorm = emb_norm[0];

    // ---- embedding ----
    const int   id = token_ids[tok];
    const float tv = __fdiv_rn((float)(id % 1000000), 1e6f);
    const float x  = tv + (float)t;

    float e[CPT];
    float ss = 0.f;
    #pragma unroll
    for (int i = 0; i < CPT; i++) {
        const int d = d0 + i;
        float angle = __fmul_rn(resonances[d], x);
        // fp64 range reduction of the f32 angle (robust to fast-math flags)
        double a = (double)angle;
        double q = rint(a * 0.15915494309189533576888376337251);
        double rd = fma(q, -6.2831853071795864769252867665590, a);
        float rf = (float)rd;            // |rf| <= pi
        float sn = __sinf(rf);
        float cs = __cosf(rf);
        float comp = fmaf(cs, 1.f + sn, sn * sn);
        float v = fmaf(comp, emb_scales[d], emb_shifts[d]);
        e[i] = v;
        ss = fmaf(v, v, ss);
    }
    float tnorm2 = block_sum(ss, red);
    float tnorm  = sqrtf(tnorm2);
    float sc_emb = (tnorm > 0.f) ? (enorm / tnorm) : 1.f;
    float e_in   = tnorm * sc_emb;       // ||emb|| after normalization
    #pragma unroll
    for (int i = 0; i < CPT; i++) e[i] *= sc_emb;

    // ---- proj = emb @ W_enc + b_enc  (d-major, float4 loads of W_enc rows) ----
    float p[24];
    #pragma unroll
    for (int k = 0; k < 24; k++) p[k] = 0.f;
    #pragma unroll
    for (int i = 0; i < CPT; i++) {
        const float4* wr = reinterpret_cast<const float4*>(W_enc + (d0 + i) * 24);
        const float ev = e[i];
        #pragma unroll
        for (int j = 0; j < 6; j++) {
            float4 w = wr[j];
            p[4 * j + 0] = fmaf(ev, w.x, p[4 * j + 0]);
            p[4 * j + 1] = fmaf(ev, w.y, p[4 * j + 1]);
            p[4 * j + 2] = fmaf(ev, w.z, p[4 * j + 2]);
            p[4 * j + 3] = fmaf(ev, w.w, p[4 * j + 3]);
        }
    }
    #pragma unroll
    for (int k = 0; k < 24; k++) smat[tid * 25 + k] = p[k];
    __syncthreads();
    if (tid < 120) {                     // stage 1: 5 partial sums per k
        const int k = tid / 5, part = tid % 5;
        float s = 0.f;
        for (int r = part; r < NTH; r += 5) s += smat[r * 25 + k];
        psum[k * 5 + part] = s;
    }
    __syncthreads();
    if (tid < 24) {                      // stage 2
        float s = b_enc[tid];
        #pragma unroll
        for (int q = 0; q < 5; q++) s += psum[tid * 5 + q];
        sproj[tid] = s;
    }
    __syncthreads();

    // ---- Golay encode -> lattice round -> rescale -> Golay decode -> threshold ----
    // G[i,l] = (l==i) + (12<=l<23)*((i+l-12)&1) + (l==23)*(i&1)
    if (tid < 32) {
        // S_odd over proj[12+j], j odd;  S_even over j even
        float S_odd  = sproj[13] + sproj[15] + sproj[17] + sproj[19] + sproj[21];
        float S_even = sproj[12] + sproj[14] + sproj[16] + sproj[18] + sproj[20] + sproj[22];
        float lat = 0.f, lsq = 0.f;
        if (tid < 12) {
            float ge = sproj[tid] + ((tid & 1) ? (S_even + sproj[23]) : S_odd);
            lat = rintf(__fdiv_rn(ge, ecc)) * ecc;   // rintf = round-half-even (matches jnp.round)
            lsq = lat * lat;
        }
        float eout2 = warp_sum(lsq);
        eout2 = __shfl_sync(0xffffffffu, eout2, 0);
        float eout = sqrtf(eout2);
        float scl  = e_in / (eout + 1e-8f) * ep;
        float latS = lat * scl;
        if (tid < 12) slatt[tid] = latS;
        if (tid == 0) s_ein2 = scl * eout;           // ||latt|| after scaling
        __syncwarp();
        float L_odd  = slatt[1] + slatt[3] + slatt[5] + slatt[7] + slatt[9] + slatt[11];
        float L_even = slatt[0] + slatt[2] + slatt[4] + slatt[6] + slatt[8] + slatt[10];
        if (tid < 24) {
            float gd;
            if (tid < 12)      gd = slatt[tid];
            else if (tid < 23) gd = ((tid - 12) & 1) ? L_even : L_odd;
            else               gd = L_odd;
            scorr[tid] = (fabsf(gd) > ecc) ? gd : 0.f;
        }
    }
    __syncthreads();

    // ---- res = corrected @ W_dec + b_dec  (coalesced float4 on d) ----
    float4 rv = reinterpret_cast<const float4*>(b_dec)[tid];
    #pragma unroll
    for (int l = 0; l < 24; l++) {
        const float c = scorr[l];
        float4 w = reinterpret_cast<const float4*>(W_dec + l * DD)[tid];
        rv.x = fmaf(c, w.x, rv.x);
        rv.y = fmaf(c, w.y, rv.y);
        rv.z = fmaf(c, w.z, rv.z);
        rv.w = fmaf(c, w.w, rv.w);
    }
    float ss2 = rv.x * rv.x + rv.y * rv.y + rv.z * rv.z + rv.w * rv.w;
    float eo2sq = block_sum(ss2, red);
    float eo2   = sqrtf(eo2sq);
    float scl2  = s_ein2 / (eo2 + 1e-8f) * ep;
    rv.x *= scl2; rv.y *= scl2; rv.z *= scl2; rv.w *= scl2;
    reinterpret_cast<float4*>(out + tok * DD)[tid] = rv;

    if (tid == 0) atomicAdd(&g_sumsq, eo2sq * scl2 * scl2);
}

// Final: out *= frac_norm * ||res||_F   (fd drops out exactly: fd/||fd|| == 1)
__global__ void k_scale(float* __restrict__ out, const float* __restrict__ frac_norm) {
    const float f = frac_norm[0] * sqrtf(g_sumsq);
    const int i = blockIdx.x * blockDim.x + threadIdx.x;   // 131072 float4's
    float4* o4 = reinterpret_cast<float4*>(out);
    float4 v = o4[i];
    v.x *= f; v.y *= f; v.z *= f; v.w *= f;
    o4[i] = v;
}

extern "C" void kernel_launch(void* const* d_in, const int* in_sizes, int n_in,
                              void* d_out, int out_size) {
    (void)in_sizes; (void)n_in; (void)out_size;
    const int*   token_ids    = (const int*)  d_in[0];
    const float* resonances   = (const float*)d_in[1];
    const float* emb_scales   = (const float*)d_in[2];
    const float* emb_shifts   = (const float*)d_in[3];
    const float* emb_norm     = (const float*)d_in[4];
    // d_in[5] scale_weights, d_in[6] fractal_bias: mathematically cancel out
    const float* frac_norm    = (const float*)d_in[7];
    const float* W_enc        = (const float*)d_in[8];
    const float* b_enc        = (const float*)d_in[9];
    const float* W_dec        = (const float*)d_in[10];
    const float* b_dec        = (const float*)d_in[11];
    const float* ecc_strength = (const float*)d_in[12];
    const float* energy_pres  = (const float*)d_in[13];
    float* out = (float*)d_out;

    k_zero<<<1, 1>>>();
    k_main<<<NTOK, NTH>>>(token_ids, resonances, emb_scales, emb_shifts, emb_norm,
                          W_enc, b_enc, W_dec, b_dec, ecc_strength, energy_pres, out);
    k_scale<<<512, 256>>>(out, frac_norm);
}

// round 2
// speedup vs baseline: 1.6511x; 1.6511x over previous
#include <cuda_runtime.h>
#include <math.h>

#define TT   512
#define DD   512
#define NTOK 1024          // B*T
#define NTH  128           // threads per token-block
#define CPT  4             // d-values per thread (NTH*CPT = DD)

// 3-term Cody-Waite split of 2*pi.
// c1 = 3217/512 (12-bit mantissa, odd) -> q*c1 exact for q <= 4096
// c2 = -2392/2^27 (9 significant bits) -> q*c2 exact
// c3 = 2pi - c1 - c2 (full f32)
#define CW_C1      6.283203125f
#define CW_C2     -1.7821788788e-5f
#define CW_C3      3.968374e-9f
#define INV_2PI    0.15915494309189533576888376337251f

__device__ __forceinline__ float warp_sum(float v) {
    v += __shfl_down_sync(0xffffffffu, v, 16);
    v += __shfl_down_sync(0xffffffffu, v, 8);
    v += __shfl_down_sync(0xffffffffu, v, 4);
    v += __shfl_down_sync(0xffffffffu, v, 2);
    v += __shfl_down_sync(0xffffffffu, v, 1);
    return v;
}

__device__ __forceinline__ float block_sum(float v, float* red) {
    int lane = threadIdx.x & 31, w = threadIdx.x >> 5;
    v = warp_sum(v);
    __syncthreads();                  // protect red reuse across calls
    if (lane == 0) red[w] = v;
    __syncthreads();
    if (w == 0) {
        float x = (lane < NTH / 32) ? red[lane] : 0.f;
        x += __shfl_down_sync(0xffffffffu, x, 2);
        x += __shfl_down_sync(0xffffffffu, x, 1);
        if (lane == 0) red[0] = x;
    }
    __syncthreads();
    return red[0];
}

__global__ __launch_bounds__(NTH) void k_fused(
    const int*   __restrict__ token_ids,
    const float* __restrict__ resonances,
    const float* __restrict__ emb_scales,
    const float* __restrict__ emb_shifts,
    const float* __restrict__ emb_norm,
    const float* __restrict__ frac_norm,
    const float* __restrict__ W_enc,     // [512,24]
    const float* __restrict__ b_enc,     // [24]
    const float* __restrict__ W_dec,     // [24,512]
    const float* __restrict__ b_dec,     // [512]
    const float* __restrict__ ecc_strength,
    const float* __restrict__ energy_pres,
    float*       __restrict__ out)
{
    __shared__ float red[NTH / 32];
    __shared__ float smat[NTH * 25];     // proj partials, stride 25 (conflict-free)
    __shared__ float psum[24 * 5];
    __shared__ float sproj[24];
    __shared__ float slatt[12];
    __shared__ float scorr[24];
    __shared__ float s_ein2;

    const int tok = blockIdx.x;          // b*T + t
    const int t   = tok & (TT - 1);
    const int tid = threadIdx.x;
    const int d0  = tid * CPT;

    const float ecc   = ecc_strength[0];
    const float ep    = energy_pres[0];
    const float enorm = emb_norm[0];
    // Global factor f = frac_norm * ||res||_F. Analytically
    // ||res_t|| = e_in2*ep*(eo2/(eo2+1e-8)) and e_in2 = e_in*ep*(eout/(eout+1e-8)),
    // e_in = enorm  =>  ||res||_F = 32*enorm*ep^2 up to O(1e-8) epsilon terms.
    const float fglob = frac_norm[0] * 32.0f * enorm * ep * ep;

    // ---- embedding (float-only Cody-Waite range reduction) ----
    const int   id = token_ids[tok];
    const float tv = __fdiv_rn((float)(id % 1000000), 1e6f);
    const float x  = tv + (float)t;

    const float4 res4 = reinterpret_cast<const float4*>(resonances + d0)[0];
    const float4 scl4 = reinterpret_cast<const float4*>(emb_scales + d0)[0];
    const float4 shf4 = reinterpret_cast<const float4*>(emb_shifts + d0)[0];
    const float rr[CPT] = {res4.x, res4.y, res4.z, res4.w};
    const float sl[CPT] = {scl4.x, scl4.y, scl4.z, scl4.w};
    const float sh[CPT] = {shf4.x, shf4.y, shf4.z, shf4.w};

    float e[CPT];
    float ss = 0.f;
    #pragma unroll
    for (int i = 0; i < CPT; i++) {
        float angle = __fmul_rn(rr[i], x);
        float q  = rintf(angle * INV_2PI);
        float rf = fmaf(q, -CW_C1, angle);   // exact
        rf       = fmaf(q, -CW_C2, rf);      // exact product
        rf       = fmaf(q, -CW_C3, rf);      // |rf| ~ [-pi, pi]
        float sn = __sinf(rf);
        float cs = __cosf(rf);
        float comp = fmaf(cs, 1.f + sn, sn * sn);
        float v = fmaf(comp, sl[i], sh[i]);
        e[i] = v;
        ss = fmaf(v, v, ss);
    }
    float tnorm2 = block_sum(ss, red);
    float tnorm  = sqrtf(tnorm2);
    float sc_emb = (tnorm > 0.f) ? (enorm / tnorm) : 1.f;
    float e_in   = tnorm * sc_emb;       // ||emb|| after normalization
    #pragma unroll
    for (int i = 0; i < CPT; i++) e[i] *= sc_emb;

    // ---- proj = emb @ W_enc + b_enc  (d-major, float4 loads of W_enc rows) ----
    float p[24];
    #pragma unroll
    for (int k = 0; k < 24; k++) p[k] = 0.f;
    #pragma unroll
    for (int i = 0; i < CPT; i++) {
        const float4* wr = reinterpret_cast<const float4*>(W_enc + (d0 + i) * 24);
        const float ev = e[i];
        #pragma unroll
        for (int j = 0; j < 6; j++) {
            float4 w = wr[j];
            p[4 * j + 0] = fmaf(ev, w.x, p[4 * j + 0]);
            p[4 * j + 1] = fmaf(ev, w.y, p[4 * j + 1]);
            p[4 * j + 2] = fmaf(ev, w.z, p[4 * j + 2]);
            p[4 * j + 3] = fmaf(ev, w.w, p[4 * j + 3]);
        }
    }
    #pragma unroll
    for (int k = 0; k < 24; k++) smat[tid * 25 + k] = p[k];
    __syncthreads();
    if (tid < 120) {                     // stage 1: 5 partial sums per k
        const int k = tid / 5, part = tid % 5;
        float s = 0.f;
        for (int r = part; r < NTH; r += 5) s += smat[r * 25 + k];
        psum[k * 5 + part] = s;
    }
    __syncthreads();
    if (tid < 24) {                      // stage 2
        float s = b_enc[tid];
        #pragma unroll
        for (int q = 0; q < 5; q++) s += psum[tid * 5 + q];
        sproj[tid] = s;
    }
    __syncthreads();

    // ---- Golay encode -> lattice round -> rescale -> Golay decode -> threshold ----
    // G[i,l] = (l==i) + (12<=l<23)*((i+l-12)&1) + (l==23)*(i&1)
    if (tid < 32) {
        float S_odd  = sproj[13] + sproj[15] + sproj[17] + sproj[19] + sproj[21];
        float S_even = sproj[12] + sproj[14] + sproj[16] + sproj[18] + sproj[20] + sproj[22];
        float lat = 0.f, lsq = 0.f;
        if (tid < 12) {
            float ge = sproj[tid] + ((tid & 1) ? (S_even + sproj[23]) : S_odd);
            lat = rintf(__fdiv_rn(ge, ecc)) * ecc;   // round-half-even, matches jnp.round
            lsq = lat * lat;
        }
        float eout2 = warp_sum(lsq);
        eout2 = __shfl_sync(0xffffffffu, eout2, 0);
        float eout = sqrtf(eout2);
        float scl  = e_in / (eout + 1e-8f) * ep;
        float latS = lat * scl;
        if (tid < 12) slatt[tid] = latS;
        if (tid == 0) s_ein2 = scl * eout;           // ||latt|| after scaling
        __syncwarp();
        float L_odd  = slatt[1] + slatt[3] + slatt[5] + slatt[7] + slatt[9] + slatt[11];
        float L_even = slatt[0] + slatt[2] + slatt[4] + slatt[6] + slatt[8] + slatt[10];
        if (tid < 24) {
            float gd;
            if (tid < 12)      gd = slatt[tid];
            else if (tid < 23) gd = ((tid - 12) & 1) ? L_even : L_odd;
            else               gd = L_odd;
            scorr[tid] = (fabsf(gd) > ecc) ? gd : 0.f;
        }
    }
    __syncthreads();

    // ---- res = corrected @ W_dec + b_dec  (coalesced float4 on d) ----
    float4 rv = reinterpret_cast<const float4*>(b_dec)[tid];
    #pragma unroll
    for (int l = 0; l < 24; l++) {
        const float c = scorr[l];
        float4 w = reinterpret_cast<const float4*>(W_dec + l * DD)[tid];
        rv.x = fmaf(c, w.x, rv.x);
        rv.y = fmaf(c, w.y, rv.y);
        rv.z = fmaf(c, w.z, rv.z);
        rv.w = fmaf(c, w.w, rv.w);
    }
    float ss2 = rv.x * rv.x + rv.y * rv.y + rv.z * rv.z + rv.w * rv.w;
    float eo2sq = block_sum(ss2, red);
    float eo2   = sqrtf(eo2sq);
    // fold global fractal factor into the per-token rescale: one fused write
    float scl2  = s_ein2 / (eo2 + 1e-8f) * ep * fglob;
    rv.x *= scl2; rv.y *= scl2; rv.z *= scl2; rv.w *= scl2;
    reinterpret_cast<float4*>(out + tok * DD)[tid] = rv;
}

extern "C" void kernel_launch(void* const* d_in, const int* in_sizes, int n_in,
                              void* d_out, int out_size) {
    (void)in_sizes; (void)n_in; (void)out_size;
    const int*   token_ids    = (const int*)  d_in[0];
    const float* resonances   = (const float*)d_in[1];
    const float* emb_scales   = (const float*)d_in[2];
    const float* emb_shifts   = (const float*)d_in[3];
    const float* emb_norm     = (const float*)d_in[4];
    // d_in[5] scale_weights, d_in[6] fractal_bias: cancel exactly in the math
    const float* frac_norm    = (const float*)d_in[7];
    const float* W_enc        = (const float*)d_in[8];
    const float* b_enc        = (const float*)d_in[9];
    const float* W_dec        = (const float*)d_in[10];
    const float* b_dec        = (const float*)d_in[11];
    const float* ecc_strength = (const float*)d_in[12];
    const float* energy_pres  = (const float*)d_in[13];
    float* out = (float*)d_out;

    k_fused<<<NTOK, NTH>>>(token_ids, resonances, emb_scales, emb_shifts, emb_norm,
                           frac_norm, W_enc, b_enc, W_dec, b_dec,
                           ecc_strength, energy_pres, out);
}